// round 7
// baseline (speedup 1.0000x reference)
#include <cuda_runtime.h>
#include <math.h>

#define DIMV 32
#define KN 16
#define NREL 60
#define MAXB 8192

// scratch (device globals)
__device__ float g_uemb [MAXB * DIMV];
__device__ int   g_e1id [MAXB * KN];
__device__ float g_attn0[MAXB * KN];
__device__ int   g_e2id [MAXB * KN * KN];
__device__ float g_attn1[MAXB * KN * KN];

__device__ __forceinline__ float sigm(float x) { return 1.f / (1.f + __expf(-x)); }

__device__ __forceinline__ float softmax16(float sc) {
    float m = sc;
    #pragma unroll
    for (int o = 8; o > 0; o >>= 1) m = fmaxf(m, __shfl_xor_sync(0xffffffffu, m, o, 16));
    float e = __expf(sc - m);
    float s = e;
    #pragma unroll
    for (int o = 8; o > 0; o >>= 1) s += __shfl_xor_sync(0xffffffffu, s, o, 16);
    return e / s;
}

__device__ __forceinline__ float udr_lookup(float u0, float u1, int rid) {
    float a = __shfl_sync(0xffffffffu, u0, rid & 31);
    float b = __shfl_sync(0xffffffffu, u1, rid & 31);
    return (rid < 32) ? a : b;
}

// ---- KA: warp per element. ids, uemb, udotr, attention weights. ----------
__global__ __launch_bounds__(256, 6) void ka_kernel(
    const int*   __restrict__ users,
    const int*   __restrict__ items,
    const float* __restrict__ emb,
    const float* __restrict__ rel,
    const int*   __restrict__ adjE,
    const int*   __restrict__ adjR,
    const int*   __restrict__ hist,
    int B)
{
    __shared__ float rels[NREL * DIMV];   // swizzled [r*32 + ((d+r)&31)]

    const int tid = threadIdx.x, lane = tid & 31, w = tid >> 5;
    #pragma unroll
    for (int i = tid; i < NREL * DIMV; i += 256) {
        int r = i >> 5, d = i & 31;
        rels[r * DIMV + ((d + r) & 31)] = __ldg(&rel[i]);
    }
    __syncthreads();

    const int b = blockIdx.x * 8 + w;
    if (b >= B) return;

    const int uid  = __ldg(&users[b]);
    const int item = __ldg(&items[b]);
    const int kl   = lane & 15;

    const int hid = __ldg(&hist[(size_t)uid  * KN + kl]);
    const int e1  = __ldg(&adjE[(size_t)item * KN + kl]);
    const int r0  = __ldg(&adjR[(size_t)item * KN + kl]);

    // user embedding: batch the 16 independent row loads
    float hv[8];
    float us = 0.f;
    #pragma unroll
    for (int h = 0; h < 2; ++h) {
        #pragma unroll
        for (int k = 0; k < 8; ++k) {
            int id = __shfl_sync(0xffffffffu, hid, h * 8 + k);
            hv[k] = __ldg(&emb[(size_t)id * DIMV + lane]);
        }
        #pragma unroll
        for (int k = 0; k < 8; ++k) us += hv[k];
    }
    const float uemb = us * (1.f / 16.f);
    g_uemb[b * DIMV + lane] = uemb;

    // udotr: lane r holds udotr[r] (u0) and udotr[r+32] (u1)
    float u0 = 0.f, u1 = 0.f;
    const int r2 = lane + 32;
    #pragma unroll
    for (int d = 0; d < DIMV; ++d) {
        float ud = __shfl_sync(0xffffffffu, uemb, d);
        u0 += ud * rels[lane * DIMV + ((d + lane) & 31)];
        if (r2 < NREL) u1 += ud * rels[r2 * DIMV + ((d + r2) & 31)];
    }

    // hop-0 attention + e1 ids
    float a0 = softmax16(udr_lookup(u0, u1, r0));
    if (lane < KN) {
        g_e1id [b * KN + lane] = e1;
        g_attn0[b * KN + lane] = a0;
    }

    // hop-2 adjacency + hop-1 attention: 8 iters x (2 rows x 16 cols)
    #pragma unroll
    for (int p = 0; p < 8; ++p) {
        int row  = 2 * p + (lane >> 4);
        int base = __shfl_sync(0xffffffffu, e1, row);
        int id   = __ldg(&adjE[(size_t)base * KN + kl]);
        int rid  = __ldg(&adjR[(size_t)base * KN + kl]);
        float a  = softmax16(udr_lookup(u0, u1, rid));
        size_t o = (size_t)b * 256 + row * KN + kl;
        g_e2id [o] = id;
        g_attn1[o] = a;
    }
}

// ---- KB': 17-warp block per element. Gathers + matvecs + final score. ----
__global__ __launch_bounds__(544, 3) void kb_kernel(
    const int*   __restrict__ items,
    const float* __restrict__ emb,
    const float* __restrict__ W,
    const float* __restrict__ bvec,
    float*       __restrict__ out,
    int B)
{
    __shared__ float Ws[DIMV * DIMV];
    __shared__ float bs[DIMV];
    __shared__ float e1s[KN][DIMV];
    __shared__ float t1s[KN][DIMV];
    __shared__ float attn0_s[KN];

    const int tid = threadIdx.x, lane = tid & 31, w = tid >> 5;
    const int b = blockIdx.x;
    if (b >= B) return;

    for (int i = tid; i < DIMV * DIMV; i += 544) Ws[i] = __ldg(&W[i]);
    if (tid < DIMV) bs[tid] = __ldg(&bvec[tid]);

    // per-warp front loads
    int   id  = 0;
    float wgt = 0.f;
    float selfv;
    if (w < KN) {
        if (lane < KN) {
            size_t o = (size_t)b * 256 + w * KN + lane;
            id  = __ldg(&g_e2id [o]);
            wgt = __ldg(&g_attn1[o]);
        }
        int selfid = __ldg(&g_e1id[b * KN + w]);
        selfv = __ldg(&emb[(size_t)selfid * DIMV + lane]);
        e1s[w][lane] = selfv;                       // share with warp 16
    } else {
        float a0 = (lane < KN) ? __ldg(&g_attn0[b * KN + lane]) : 0.f;
        if (lane < KN) attn0_s[lane] = a0;
        int item = __ldg(&items[b]);
        selfv = __ldg(&emb[(size_t)item * DIMV + lane]);
    }
    __syncthreads();   // Ws, bs, e1s, attn0_s ready

    const float bl = bs[lane];
    float t0 = 0.f;

    if (w < KN) {
        // 16 independent gathers, explicitly batched for MLP
        float val[8], acc = 0.f;
        #pragma unroll
        for (int h = 0; h < 2; ++h) {
            #pragma unroll
            for (int k = 0; k < 8; ++k) {
                int ik = __shfl_sync(0xffffffffu, id, h * 8 + k);
                val[k] = __ldg(&emb[(size_t)ik * DIMV + lane]);
            }
            #pragma unroll
            for (int k = 0; k < 8; ++k)
                acc += __shfl_sync(0xffffffffu, wgt, h * 8 + k) * val[k];
        }
        float x = selfv + acc;
        float y = bl;
        #pragma unroll
        for (int j = 0; j < DIMV; ++j)
            y += __shfl_sync(0xffffffffu, x, j) * Ws[j * DIMV + lane];
        t1s[w][lane] = sigm(y);
    } else {
        // hop-0 node: aggregate from shared e1 rows (no re-gather)
        float acc0 = 0.f;
        #pragma unroll
        for (int k = 0; k < KN; ++k) acc0 += attn0_s[k] * e1s[k][lane];
        float x0 = selfv + acc0;
        float y0 = bl;
        #pragma unroll
        for (int j = 0; j < DIMV; ++j)
            y0 += __shfl_sync(0xffffffffu, x0, j) * Ws[j * DIMV + lane];
        t0 = sigm(y0);
    }
    __syncthreads();   // t1s ready

    if (w == KN) {
        float accf = 0.f;
        #pragma unroll
        for (int k = 0; k < KN; ++k) accf += attn0_s[k] * t1s[k][lane];
        float xf = t0 + accf;
        float yf = bl;
        #pragma unroll
        for (int j = 0; j < DIMV; ++j)
            yf += __shfl_sync(0xffffffffu, xf, j) * Ws[j * DIMV + lane];
        float f = tanhf(yf);

        float s = __ldg(&g_uemb[b * DIMV + lane]) * f;
        #pragma unroll
        for (int o = 16; o > 0; o >>= 1) s += __shfl_xor_sync(0xffffffffu, s, o);
        if (lane == 0) out[b] = sigm(s);
    }
}

extern "C" void kernel_launch(void* const* d_in, const int* in_sizes, int n_in,
                              void* d_out, int out_size) {
    const int*   users        = (const int*)  d_in[0];
    const int*   items        = (const int*)  d_in[1];
    const float* entity_emb   = (const float*)d_in[2];
    const float* relation_emb = (const float*)d_in[3];
    const int*   adj_entity   = (const int*)  d_in[4];
    const int*   adj_relation = (const int*)  d_in[5];
    const int*   user_history = (const int*)  d_in[6];
    const float* W            = (const float*)d_in[7];
    const float* b            = (const float*)d_in[8];
    float* out = (float*)d_out;

    int B = in_sizes[0];
    ka_kernel<<<(B + 7) / 8, 256>>>(users, items, entity_emb, relation_emb,
                                    adj_entity, adj_relation, user_history, B);
    kb_kernel<<<B, 544>>>(items, entity_emb, W, b, out, B);
}